// round 16
// baseline (speedup 1.0000x reference)
#include <cuda_runtime.h>
#include <cuda_fp16.h>
#include <math.h>

#define Mpts 100000
#define Bb 8
#define Kk 512
#define Nn 256

#define BETA_F 13.85510032f       // pi*sqrt((J/ALPHA*(ALPHA-0.5))^2 - 0.8)
#define KSC 81.48733086f          // K/(2*pi)
#define PIJK 0.03681553891f       // pi*J/K

// fp16 grid: [cell][b], 8 complex-half per cell = 32B. 8 MB total.
// Statically zero-initialized for the first run; each fftA block re-zeroes the
// row it consumed, so every graph replay starts from a zero grid.
__device__ __align__(16) __half2 g_gridh[Kk * Kk * Bb];
// row-FFT output, pruned: [b][row(0..511)][j(0..255)]. 8 MB.
__device__ float2 g_grid2[Bb * Kk * Nn];
// real image after col-FFT + apod, TRANSPOSED: [b][c][r]. 2 MB.
__device__ float g_img[Bb * Nn * Nn];
__device__ int g_mm_i[2 * Bb];

// ---------------- helpers ----------------
__device__ __forceinline__ float2 cmul(float2 a, float2 b) {
    return make_float2(a.x * b.x - a.y * b.y, a.x * b.y + a.y * b.x);
}
__device__ __forceinline__ float2 cadd(float2 a, float2 b) { return make_float2(a.x + b.x, a.y + b.y); }
__device__ __forceinline__ float2 csub(float2 a, float2 b) { return make_float2(a.x - b.x, a.y - b.y); }

__device__ __forceinline__ int fenc(float v) {
    int b = __float_as_int(v);
    return b >= 0 ? b : (b ^ 0x7fffffff);
}

// Bessel I0 (A&S 9.8.1/9.8.2)
__device__ __forceinline__ float i0f(float x) {
    float ax = fabsf(x);
    if (ax < 3.75f) {
        float t = x / 3.75f;
        t *= t;
        return 1.0f + t * (3.5156229f + t * (3.0899424f + t * (1.2067492f +
               t * (0.2659732f + t * (0.0360768f + t * 0.0045813f)))));
    } else {
        float t = 3.75f / ax;
        float p = 0.39894228f + t * (0.01328592f + t * (0.00225319f +
                  t * (-0.00157565f + t * (0.00916281f + t * (-0.02057706f +
                  t * (0.02635537f + t * (-0.01647633f + t * 0.00392377f)))))));
        return (expf(ax) / sqrtf(ax)) * p;
    }
}

__device__ __forceinline__ float apodinv(int n) {
    float x = (float)(n - 128) * PIJK;
    float a = BETA_F * BETA_F - x * x;
    float sq = sqrtf(a);
    return sq / sinhf(sq);
}

// ---------------- gridding scatter: 2 threads per point, fp16 v4 REDs -------
// Also initializes g_mm_i (block 0) — ordered before fftB by serialization.
__global__ void __launch_bounds__(256) scatter_k(
    const float* __restrict__ yr, const float* __restrict__ yi,
    const float* __restrict__ wt, const float* __restrict__ uv) {
    int gid = blockIdx.x * 256 + threadIdx.x;
    if (gid < 2 * Bb)
        g_mm_i[gid] = (gid & 1) ? (int)0x80000000 : 0x7fffffff;
    int m = gid >> 1, q = gid & 1;   // q selects batches {4q..4q+3} (16B half-cell)
    if (m >= Mpts) return;

    float u = uv[2 * m], v = uv[2 * m + 1];
    float kfu = u * KSC, kfv = v * KSC;
    float fbu = floorf(kfu), fbv = floorf(kfv);
    int bu = (int)fbu, bv = (int)fbv;
    float fru = kfu - fbu, frv = kfv - fbv;

    float winv = 1.0f / i0f(BETA_F);

    float wu[6], wv[6];
    int iu[6], iv[6];
#pragma unroll
    for (int o = 0; o < 6; o++) {
        float du = (float)(o - 2) - fru;
        float dv = (float)(o - 2) - frv;
        float uu = du * (1.0f / 3.0f);
        float vv = dv * (1.0f / 3.0f);
        wu[o] = i0f(BETA_F * sqrtf(fmaxf(1.0f - uu * uu, 0.0f)));
        wv[o] = i0f(BETA_F * sqrtf(fmaxf(1.0f - vv * vv, 0.0f)));
        iu[o] = (bu + (o - 2) + Kk) & (Kk - 1);
        iv[o] = (bv + (o - 2) + Kk) & (Kk - 1);
    }

    float wm = wt[m] * winv * winv;   // fold both kernel norms into the data
    int b0 = 4 * q;
    float r0 = yr[(b0 + 0) * Mpts + m] * wm, i0v = yi[(b0 + 0) * Mpts + m] * wm;
    float r1 = yr[(b0 + 1) * Mpts + m] * wm, i1 = yi[(b0 + 1) * Mpts + m] * wm;
    float r2 = yr[(b0 + 2) * Mpts + m] * wm, i2 = yi[(b0 + 2) * Mpts + m] * wm;
    float r3 = yr[(b0 + 3) * Mpts + m] * wm, i3 = yi[(b0 + 3) * Mpts + m] * wm;

#pragma unroll
    for (int j1 = 0; j1 < 6; j1++) {
        int rb = iu[j1] << 9;
        float w1 = wu[j1];
#pragma unroll
        for (int j2 = 0; j2 < 6; j2++) {
            float ww = w1 * wv[j2];
            __half2 h0 = __floats2half2_rn(r0 * ww, i0v * ww);
            __half2 h1 = __floats2half2_rn(r1 * ww, i1 * ww);
            __half2 h2 = __floats2half2_rn(r2 * ww, i2 * ww);
            __half2 h3 = __floats2half2_rn(r3 * ww, i3 * ww);
            unsigned u0 = *reinterpret_cast<unsigned*>(&h0);
            unsigned u1 = *reinterpret_cast<unsigned*>(&h1);
            unsigned u2 = *reinterpret_cast<unsigned*>(&h2);
            unsigned u3 = *reinterpret_cast<unsigned*>(&h3);
            __half2* p = g_gridh + (((unsigned)(rb + iv[j2])) << 3) + (q << 2);
            asm volatile("red.global.add.noftz.v4.f16x2 [%0], {%1,%2,%3,%4};"
                         :: "l"(p), "r"(u0), "r"(u1), "r"(u2), "r"(u3) : "memory");
        }
    }
}

// ---------------- 512-pt inverse FFT, radix-8 Stockham, 64 threads per FFT ----
#define PIDX(i) ((i) + ((i) >> 3))

__device__ __forceinline__ void fft8p(const float2* x, float2* y) {
    const float C = 0.70710678118654752f;
    float2 a0 = cadd(x[0], x[4]), a4 = csub(x[0], x[4]);
    float2 a1 = cadd(x[1], x[5]), t5 = csub(x[1], x[5]);
    float2 a2 = cadd(x[2], x[6]), t6 = csub(x[2], x[6]);
    float2 a3 = cadd(x[3], x[7]), t7 = csub(x[3], x[7]);
    float2 a5 = make_float2(C * (t5.x - t5.y), C * (t5.x + t5.y));    // *W8   (s=+1)
    float2 a6 = make_float2(-t6.y, t6.x);                              // *i
    float2 a7 = make_float2(-C * (t7.x + t7.y), C * (t7.x - t7.y));    // *W8^3

    float2 b0 = cadd(a0, a2), b2 = csub(a0, a2);
    float2 b1 = cadd(a1, a3), t3 = csub(a1, a3);
    float2 b3 = make_float2(-t3.y, t3.x);                              // *i
    float2 b4 = cadd(a4, a6), b6 = csub(a4, a6);
    float2 b5 = cadd(a5, a7), u7 = csub(a5, a7);
    float2 b7 = make_float2(-u7.y, u7.x);                              // *i

    y[0] = cadd(b0, b1); y[4] = csub(b0, b1);
    y[2] = cadd(b2, b3); y[6] = csub(b2, b3);
    y[1] = cadd(b4, b5); y[5] = csub(b4, b5);
    y[3] = cadd(b6, b7); y[7] = csub(b6, b7);
}

__device__ __forceinline__ void twiddle8(float2* x, float ang) {
    float2 w1; __sincosf(ang, &w1.y, &w1.x);
    float2 w = w1;
    x[1] = cmul(x[1], w);
#pragma unroll
    for (int i = 2; i < 8; i++) { w = cmul(w, w1); x[i] = cmul(x[i], w); }
}

__device__ __forceinline__ void fft512(float2* S, int t, float2* y) {
    float2 x[8];
#pragma unroll
    for (int i = 0; i < 8; i++) x[i] = S[PIDX(t + 64 * i)];
    fft8p(x, y);
    __syncthreads();
#pragma unroll
    for (int i = 0; i < 8; i++) S[PIDX(8 * t + i)] = y[i];
    __syncthreads();
#pragma unroll
    for (int i = 0; i < 8; i++) x[i] = S[PIDX(t + 64 * i)];
    {
        int k = t & 7;
        twiddle8(x, 0.09817477042f * (float)k);   // 2*pi/64
    }
    fft8p(x, y);
    __syncthreads();
    {
        int k = t & 7, g = t >> 3;
#pragma unroll
        for (int i = 0; i < 8; i++) S[PIDX(g * 64 + i * 8 + k)] = y[i];
    }
    __syncthreads();
#pragma unroll
    for (int i = 0; i < 8; i++) x[i] = S[PIDX(t + 64 * i)];
    twiddle8(x, 0.01227184630f * (float)t);       // 2*pi/512
    fft8p(x, y);
}

// ---------------- FFT pass A: along axis 2 (columns). 8 batches / block -----
// PDL dependent: syncs on scatter's memory before reading/zeroing g_gridh.
__global__ void __launch_bounds__(512) fftA_k() {
    __shared__ float2 s[8 * 577];
    int row = blockIdx.x;
    uint4* src = reinterpret_cast<uint4*>(g_gridh + (size_t)row * (Kk * Bb));

    cudaGridDependencySynchronize();

    for (int idx = threadIdx.x; idx < Kk * 2; idx += 512) {
        int col = idx >> 1, q = idx & 1;      // uint4 = 4 complex-halves (batches 4q..4q+3)
        uint4 val = src[idx];
        __half2 h0 = *reinterpret_cast<__half2*>(&val.x);
        __half2 h1 = *reinterpret_cast<__half2*>(&val.y);
        __half2 h2 = *reinterpret_cast<__half2*>(&val.z);
        __half2 h3 = *reinterpret_cast<__half2*>(&val.w);
        int bq = 4 * q;
        s[(bq + 0) * 577 + PIDX(col)] = __half22float2(h0);
        s[(bq + 1) * 577 + PIDX(col)] = __half22float2(h1);
        s[(bq + 2) * 577 + PIDX(col)] = __half22float2(h2);
        s[(bq + 3) * 577 + PIDX(col)] = __half22float2(h3);
    }
    __syncthreads();

    // zero this row for the next replay (all reads of it completed above)
    {
        uint4 z = make_uint4(0u, 0u, 0u, 0u);
        src[threadIdx.x] = z;
        src[threadIdx.x + 512] = z;
    }

    int b = threadIdx.x >> 6, t = threadIdx.x & 63;
    float2 y[8];
    fft512(s + b * 577, t, y);

    float2* dst = g_grid2 + ((size_t)b * Kk + row) * Nn;
#pragma unroll
    for (int i = 0; i < 8; i++) {
        int n = i * 64 + t;
        int j = (n < 128) ? (n + 128) : (n - 384);
        if (n < 128 || n >= 384) dst[j] = y[i];
    }
}

// ---------------- FFT pass B: along axis 1 (rows). 4 columns / block --------
// PDL dependent: syncs on fftA's memory before reading g_grid2.
__global__ void __launch_bounds__(256) fftB_k() {
    __shared__ float2 s[4 * 577];
    __shared__ float swn[8], swx[8];
    int bj = blockIdx.x;            // b*64 + jgroup
    int b = bj >> 6, j0 = (bj & 63) << 2;
    const float2* src = g_grid2 + (size_t)b * Kk * Nn + j0;

    cudaGridDependencySynchronize();

    for (int idx = threadIdx.x; idx < Kk * 4; idx += 256) {
        int row = idx >> 2, jj = idx & 3;
        s[jj * 577 + PIDX(row)] = src[(size_t)row * Nn + jj];
    }
    __syncthreads();

    int f = threadIdx.x >> 6, t = threadIdx.x & 63;
    float2 y[8];
    fft512(s + f * 577, t, y);

    int c = j0 + f;
    float ac = apodinv(c);
    float* dst = g_img + ((size_t)b * Nn + c) * Nn;   // [b][c][r]
    float mn = 3.4e38f, mx = -3.4e38f;
#pragma unroll
    for (int i = 0; i < 8; i++) {
        int n = i * 64 + t;
        if (n < 128 || n >= 384) {
            int jr = (n < 128) ? (n + 128) : (n - 384);
            float val = y[i].x * apodinv(jr) * ac;
            dst[jr] = val;
            mn = fminf(mn, val);
            mx = fmaxf(mx, val);
        }
    }
#pragma unroll
    for (int off = 16; off; off >>= 1) {
        mn = fminf(mn, __shfl_xor_sync(0xffffffffu, mn, off));
        mx = fmaxf(mx, __shfl_xor_sync(0xffffffffu, mx, off));
    }
    int w = threadIdx.x >> 5;
    if ((threadIdx.x & 31) == 0) { swn[w] = mn; swx[w] = mx; }
    __syncthreads();
    if (threadIdx.x == 0) {
#pragma unroll
        for (int k = 1; k < 8; k++) { mn = fminf(mn, swn[k]); mx = fmaxf(mx, swx[k]); }
        atomicMin(&g_mm_i[2 * b], fenc(mn));
        atomicMax(&g_mm_i[2 * b + 1], fenc(mx));
    }
}

// ---------------- normalize + transpose [b][c][r] -> out [b][r][c] ----------
// float4 loads and stores via padded smem tile; PDL dependent on fftB.
__global__ void __launch_bounds__(256) norm_k(float* __restrict__ out) {
    __shared__ float tile[32][33];
    int b = blockIdx.z;
    int c0 = blockIdx.x * 32, r0 = blockIdx.y * 32;
    int t = threadIdx.x;
    int row = t >> 3, vec = t & 7;   // 32 rows x 8 float4

    cudaGridDependencySynchronize();

    int emn = g_mm_i[2 * b], emx = g_mm_i[2 * b + 1];
    float mn = __int_as_float(emn < 0 ? (emn ^ 0x7fffffff) : emn);
    float mx = __int_as_float(emx < 0 ? (emx ^ 0x7fffffff) : emx);
    float inv = 1.0f / (mx - mn);

    const float* src = g_img + ((size_t)b << 16);
    float* dst = out + ((size_t)b << 16);

    // load: tile[c-local][r-local] from [b][c][r], float4 along r
    float4 v = *reinterpret_cast<const float4*>(src + (size_t)(c0 + row) * Nn + r0 + vec * 4);
    tile[row][vec * 4 + 0] = v.x;
    tile[row][vec * 4 + 1] = v.y;
    tile[row][vec * 4 + 2] = v.z;
    tile[row][vec * 4 + 3] = v.w;
    __syncthreads();

    // store: out[b][r][c], float4 along c (transposed read from tile)
    float4 o;
    o.x = (tile[vec * 4 + 0][row] - mn) * inv;
    o.y = (tile[vec * 4 + 1][row] - mn) * inv;
    o.z = (tile[vec * 4 + 2][row] - mn) * inv;
    o.w = (tile[vec * 4 + 3][row] - mn) * inv;
    *reinterpret_cast<float4*>(dst + (size_t)(r0 + row) * Nn + c0 + vec * 4) = o;
}

// ---------------- launch ----------------
template <typename F, typename... Args>
static inline void launch_pdl(F* fn, dim3 grid, dim3 block, Args... args) {
    cudaLaunchConfig_t cfg = {};
    cfg.gridDim = grid;
    cfg.blockDim = block;
    cfg.dynamicSmemBytes = 0;
    cfg.stream = 0;
    cudaLaunchAttribute attr[1];
    attr[0].id = cudaLaunchAttributeProgrammaticStreamSerialization;
    attr[0].val.programmaticStreamSerializationAllowed = 1;
    cfg.attrs = attr;
    cfg.numAttrs = 1;
    cudaLaunchKernelEx(&cfg, fn, args...);
}

extern "C" void kernel_launch(void* const* d_in, const int* in_sizes, int n_in,
                              void* d_out, int out_size) {
    const float* yr = (const float*)d_in[0];
    const float* yi = (const float*)d_in[1];
    const float* wt = (const float*)d_in[2];
    const float* uv = (const float*)d_in[3];
    float* out = (float*)d_out;

    scatter_k<<<(2 * Mpts + 255) / 256, 256>>>(yr, yi, wt, uv);
    launch_pdl(fftA_k, dim3(Kk), dim3(512));
    launch_pdl(fftB_k, dim3(Bb * (Nn / 4)), dim3(256));
    launch_pdl(norm_k, dim3(8, 8, 8), dim3(256), out);
}

// round 17
// speedup vs baseline: 1.5628x; 1.5628x over previous
#include <cuda_runtime.h>
#include <cuda_fp16.h>
#include <math.h>

#define Mpts 100000
#define Bb 8
#define Kk 512
#define Nn 256

#define BETA_F 13.85510032f       // pi*sqrt((J/ALPHA*(ALPHA-0.5))^2 - 0.8)
#define KSC 81.48733086f          // K/(2*pi)
#define PIJK 0.03681553891f       // pi*J/K

// fp16 grid: [cell][b], 8 complex-half per cell = 32B. 8 MB total.
// Statically zero-initialized for the first run; each fftA block re-zeroes the
// row it consumed, so every graph replay starts from a zero grid.
__device__ __align__(16) __half2 g_gridh[Kk * Kk * Bb];
// row-FFT output, pruned: [b][row(0..511)][j(0..255)]. 8 MB.
__device__ float2 g_grid2[Bb * Kk * Nn];
// real image after col-FFT + apod, TRANSPOSED: [b][c][r]. 2 MB.
__device__ float g_img[Bb * Nn * Nn];
__device__ int g_mm_i[2 * Bb];

// ---------------- helpers ----------------
__device__ __forceinline__ float2 cmul(float2 a, float2 b) {
    return make_float2(a.x * b.x - a.y * b.y, a.x * b.y + a.y * b.x);
}
__device__ __forceinline__ float2 cadd(float2 a, float2 b) { return make_float2(a.x + b.x, a.y + b.y); }
__device__ __forceinline__ float2 csub(float2 a, float2 b) { return make_float2(a.x - b.x, a.y - b.y); }

__device__ __forceinline__ int fenc(float v) {
    int b = __float_as_int(v);
    return b >= 0 ? b : (b ^ 0x7fffffff);
}

// Bessel I0 (A&S 9.8.1/9.8.2)
__device__ __forceinline__ float i0f(float x) {
    float ax = fabsf(x);
    if (ax < 3.75f) {
        float t = x / 3.75f;
        t *= t;
        return 1.0f + t * (3.5156229f + t * (3.0899424f + t * (1.2067492f +
               t * (0.2659732f + t * (0.0360768f + t * 0.0045813f)))));
    } else {
        float t = 3.75f / ax;
        float p = 0.39894228f + t * (0.01328592f + t * (0.00225319f +
                  t * (-0.00157565f + t * (0.00916281f + t * (-0.02057706f +
                  t * (0.02635537f + t * (-0.01647633f + t * 0.00392377f)))))));
        return (expf(ax) / sqrtf(ax)) * p;
    }
}

__device__ __forceinline__ float apodinv(int n) {
    float x = (float)(n - 128) * PIJK;
    float a = BETA_F * BETA_F - x * x;
    float sq = sqrtf(a);
    return sq / sinhf(sq);
}

// ---------------- gridding scatter: 2 threads per point, fp16 v4 REDs -------
// Also initializes g_mm_i — ordered before fftB's atomics by serialization.
__global__ void __launch_bounds__(256) scatter_k(
    const float* __restrict__ yr, const float* __restrict__ yi,
    const float* __restrict__ wt, const float* __restrict__ uv) {
    int gid = blockIdx.x * 256 + threadIdx.x;
    if (gid < 2 * Bb)
        g_mm_i[gid] = (gid & 1) ? (int)0x80000000 : 0x7fffffff;
    int m = gid >> 1, q = gid & 1;   // q selects batches {4q..4q+3} (16B half-cell)
    if (m >= Mpts) return;

    float u = uv[2 * m], v = uv[2 * m + 1];
    float kfu = u * KSC, kfv = v * KSC;
    float fbu = floorf(kfu), fbv = floorf(kfv);
    int bu = (int)fbu, bv = (int)fbv;
    float fru = kfu - fbu, frv = kfv - fbv;

    float winv = 1.0f / i0f(BETA_F);

    float wu[6], wv[6];
    int iu[6], iv[6];
#pragma unroll
    for (int o = 0; o < 6; o++) {
        float du = (float)(o - 2) - fru;
        float dv = (float)(o - 2) - frv;
        float uu = du * (1.0f / 3.0f);
        float vv = dv * (1.0f / 3.0f);
        wu[o] = i0f(BETA_F * sqrtf(fmaxf(1.0f - uu * uu, 0.0f)));
        wv[o] = i0f(BETA_F * sqrtf(fmaxf(1.0f - vv * vv, 0.0f)));
        iu[o] = (bu + (o - 2) + Kk) & (Kk - 1);
        iv[o] = (bv + (o - 2) + Kk) & (Kk - 1);
    }

    float wm = wt[m] * winv * winv;   // fold both kernel norms into the data
    int b0 = 4 * q;
    float r0 = yr[(b0 + 0) * Mpts + m] * wm, i0v = yi[(b0 + 0) * Mpts + m] * wm;
    float r1 = yr[(b0 + 1) * Mpts + m] * wm, i1 = yi[(b0 + 1) * Mpts + m] * wm;
    float r2 = yr[(b0 + 2) * Mpts + m] * wm, i2 = yi[(b0 + 2) * Mpts + m] * wm;
    float r3 = yr[(b0 + 3) * Mpts + m] * wm, i3 = yi[(b0 + 3) * Mpts + m] * wm;

#pragma unroll
    for (int j1 = 0; j1 < 6; j1++) {
        int rb = iu[j1] << 9;
        float w1 = wu[j1];
#pragma unroll
        for (int j2 = 0; j2 < 6; j2++) {
            float ww = w1 * wv[j2];
            __half2 h0 = __floats2half2_rn(r0 * ww, i0v * ww);
            __half2 h1 = __floats2half2_rn(r1 * ww, i1 * ww);
            __half2 h2 = __floats2half2_rn(r2 * ww, i2 * ww);
            __half2 h3 = __floats2half2_rn(r3 * ww, i3 * ww);
            unsigned u0 = *reinterpret_cast<unsigned*>(&h0);
            unsigned u1 = *reinterpret_cast<unsigned*>(&h1);
            unsigned u2 = *reinterpret_cast<unsigned*>(&h2);
            unsigned u3 = *reinterpret_cast<unsigned*>(&h3);
            __half2* p = g_gridh + (((unsigned)(rb + iv[j2])) << 3) + (q << 2);
            asm volatile("red.global.add.noftz.v4.f16x2 [%0], {%1,%2,%3,%4};"
                         :: "l"(p), "r"(u0), "r"(u1), "r"(u2), "r"(u3) : "memory");
        }
    }
}

// ---------------- 512-pt inverse FFT, radix-8 Stockham, 64 threads per FFT ----
#define PIDX(i) ((i) + ((i) >> 3))

__device__ __forceinline__ void fft8p(const float2* x, float2* y) {
    const float C = 0.70710678118654752f;
    float2 a0 = cadd(x[0], x[4]), a4 = csub(x[0], x[4]);
    float2 a1 = cadd(x[1], x[5]), t5 = csub(x[1], x[5]);
    float2 a2 = cadd(x[2], x[6]), t6 = csub(x[2], x[6]);
    float2 a3 = cadd(x[3], x[7]), t7 = csub(x[3], x[7]);
    float2 a5 = make_float2(C * (t5.x - t5.y), C * (t5.x + t5.y));    // *W8   (s=+1)
    float2 a6 = make_float2(-t6.y, t6.x);                              // *i
    float2 a7 = make_float2(-C * (t7.x + t7.y), C * (t7.x - t7.y));    // *W8^3

    float2 b0 = cadd(a0, a2), b2 = csub(a0, a2);
    float2 b1 = cadd(a1, a3), t3 = csub(a1, a3);
    float2 b3 = make_float2(-t3.y, t3.x);                              // *i
    float2 b4 = cadd(a4, a6), b6 = csub(a4, a6);
    float2 b5 = cadd(a5, a7), u7 = csub(a5, a7);
    float2 b7 = make_float2(-u7.y, u7.x);                              // *i

    y[0] = cadd(b0, b1); y[4] = csub(b0, b1);
    y[2] = cadd(b2, b3); y[6] = csub(b2, b3);
    y[1] = cadd(b4, b5); y[5] = csub(b4, b5);
    y[3] = cadd(b6, b7); y[7] = csub(b6, b7);
}

__device__ __forceinline__ void twiddle8(float2* x, float ang) {
    float2 w1; __sincosf(ang, &w1.y, &w1.x);
    float2 w = w1;
    x[1] = cmul(x[1], w);
#pragma unroll
    for (int i = 2; i < 8; i++) { w = cmul(w, w1); x[i] = cmul(x[i], w); }
}

__device__ __forceinline__ void fft512(float2* S, int t, float2* y) {
    float2 x[8];
#pragma unroll
    for (int i = 0; i < 8; i++) x[i] = S[PIDX(t + 64 * i)];
    fft8p(x, y);
    __syncthreads();
#pragma unroll
    for (int i = 0; i < 8; i++) S[PIDX(8 * t + i)] = y[i];
    __syncthreads();
#pragma unroll
    for (int i = 0; i < 8; i++) x[i] = S[PIDX(t + 64 * i)];
    {
        int k = t & 7;
        twiddle8(x, 0.09817477042f * (float)k);   // 2*pi/64
    }
    fft8p(x, y);
    __syncthreads();
    {
        int k = t & 7, g = t >> 3;
#pragma unroll
        for (int i = 0; i < 8; i++) S[PIDX(g * 64 + i * 8 + k)] = y[i];
    }
    __syncthreads();
#pragma unroll
    for (int i = 0; i < 8; i++) x[i] = S[PIDX(t + 64 * i)];
    twiddle8(x, 0.01227184630f * (float)t);       // 2*pi/512
    fft8p(x, y);
}

// ---------------- FFT pass A: along axis 2 (columns). 8 batches / block -----
// After staging its grid row in smem, each block zeroes that row in GMEM for
// the next graph replay (stores overlap the FFT compute).
__global__ void __launch_bounds__(512) fftA_k() {
    __shared__ float2 s[8 * 577];
    int row = blockIdx.x;
    uint4* src = reinterpret_cast<uint4*>(g_gridh + (size_t)row * (Kk * Bb));
    for (int idx = threadIdx.x; idx < Kk * 2; idx += 512) {
        int col = idx >> 1, q = idx & 1;      // uint4 = 4 complex-halves (batches 4q..4q+3)
        uint4 val = src[idx];
        __half2 h0 = *reinterpret_cast<__half2*>(&val.x);
        __half2 h1 = *reinterpret_cast<__half2*>(&val.y);
        __half2 h2 = *reinterpret_cast<__half2*>(&val.z);
        __half2 h3 = *reinterpret_cast<__half2*>(&val.w);
        int bq = 4 * q;
        s[(bq + 0) * 577 + PIDX(col)] = __half22float2(h0);
        s[(bq + 1) * 577 + PIDX(col)] = __half22float2(h1);
        s[(bq + 2) * 577 + PIDX(col)] = __half22float2(h2);
        s[(bq + 3) * 577 + PIDX(col)] = __half22float2(h3);
    }
    __syncthreads();

    // zero this row for the next replay (all reads of it completed above)
    {
        uint4 z = make_uint4(0u, 0u, 0u, 0u);
        src[threadIdx.x] = z;
        src[threadIdx.x + 512] = z;
    }

    int b = threadIdx.x >> 6, t = threadIdx.x & 63;
    float2 y[8];
    fft512(s + b * 577, t, y);

    float2* dst = g_grid2 + ((size_t)b * Kk + row) * Nn;
#pragma unroll
    for (int i = 0; i < 8; i++) {
        int n = i * 64 + t;
        int j = (n < 128) ? (n + 128) : (n - 384);
        if (n < 128 || n >= 384) dst[j] = y[i];
    }
}

// ---------------- FFT pass B: along axis 1 (rows). 4 columns / block --------
__global__ void __launch_bounds__(256) fftB_k() {
    __shared__ float2 s[4 * 577];
    __shared__ float swn[8], swx[8];
    int bj = blockIdx.x;            // b*64 + jgroup
    int b = bj >> 6, j0 = (bj & 63) << 2;
    const float2* src = g_grid2 + (size_t)b * Kk * Nn + j0;
    for (int idx = threadIdx.x; idx < Kk * 4; idx += 256) {
        int row = idx >> 2, jj = idx & 3;
        s[jj * 577 + PIDX(row)] = src[(size_t)row * Nn + jj];
    }
    __syncthreads();

    int f = threadIdx.x >> 6, t = threadIdx.x & 63;
    float2 y[8];
    fft512(s + f * 577, t, y);

    int c = j0 + f;
    float ac = apodinv(c);
    float* dst = g_img + ((size_t)b * Nn + c) * Nn;   // [b][c][r]
    float mn = 3.4e38f, mx = -3.4e38f;
#pragma unroll
    for (int i = 0; i < 8; i++) {
        int n = i * 64 + t;
        if (n < 128 || n >= 384) {
            int jr = (n < 128) ? (n + 128) : (n - 384);
            float val = y[i].x * apodinv(jr) * ac;
            dst[jr] = val;
            mn = fminf(mn, val);
            mx = fmaxf(mx, val);
        }
    }
#pragma unroll
    for (int off = 16; off; off >>= 1) {
        mn = fminf(mn, __shfl_xor_sync(0xffffffffu, mn, off));
        mx = fmaxf(mx, __shfl_xor_sync(0xffffffffu, mx, off));
    }
    int w = threadIdx.x >> 5;
    if ((threadIdx.x & 31) == 0) { swn[w] = mn; swx[w] = mx; }
    __syncthreads();
    if (threadIdx.x == 0) {
#pragma unroll
        for (int k = 1; k < 8; k++) { mn = fminf(mn, swn[k]); mx = fmaxf(mx, swx[k]); }
        atomicMin(&g_mm_i[2 * b], fenc(mn));
        atomicMax(&g_mm_i[2 * b + 1], fenc(mx));
    }
}

// ---------------- normalize + transpose [b][c][r] -> out [b][r][c] ----------
// float4 loads and stores via padded 32x33 smem tile (conflict-free both ways).
__global__ void __launch_bounds__(256) norm_k(float* __restrict__ out) {
    __shared__ float tile[32][33];
    int b = blockIdx.z;
    int c0 = blockIdx.x * 32, r0 = blockIdx.y * 32;
    int t = threadIdx.x;
    int row = t >> 3, vec = t & 7;   // 32 rows x 8 float4

    int emn = g_mm_i[2 * b], emx = g_mm_i[2 * b + 1];
    float mn = __int_as_float(emn < 0 ? (emn ^ 0x7fffffff) : emn);
    float mx = __int_as_float(emx < 0 ? (emx ^ 0x7fffffff) : emx);
    float inv = 1.0f / (mx - mn);

    const float* src = g_img + ((size_t)b << 16);
    float* dst = out + ((size_t)b << 16);

    // load: tile[c-local][r-local] from [b][c][r], float4 along r
    float4 v = *reinterpret_cast<const float4*>(src + (size_t)(c0 + row) * Nn + r0 + vec * 4);
    tile[row][vec * 4 + 0] = v.x;
    tile[row][vec * 4 + 1] = v.y;
    tile[row][vec * 4 + 2] = v.z;
    tile[row][vec * 4 + 3] = v.w;
    __syncthreads();

    // store: out[b][r][c], float4 along c (transposed read from tile)
    float4 o;
    o.x = (tile[vec * 4 + 0][row] - mn) * inv;
    o.y = (tile[vec * 4 + 1][row] - mn) * inv;
    o.z = (tile[vec * 4 + 2][row] - mn) * inv;
    o.w = (tile[vec * 4 + 3][row] - mn) * inv;
    *reinterpret_cast<float4*>(dst + (size_t)(r0 + row) * Nn + c0 + vec * 4) = o;
}

extern "C" void kernel_launch(void* const* d_in, const int* in_sizes, int n_in,
                              void* d_out, int out_size) {
    const float* yr = (const float*)d_in[0];
    const float* yi = (const float*)d_in[1];
    const float* wt = (const float*)d_in[2];
    const float* uv = (const float*)d_in[3];
    float* out = (float*)d_out;

    scatter_k<<<(2 * Mpts + 255) / 256, 256>>>(yr, yi, wt, uv);
    fftA_k<<<Kk, 512>>>();
    fftB_k<<<Bb * (Nn / 4), 256>>>();
    norm_k<<<dim3(8, 8, 8), 256>>>(out);
}